// round 14
// baseline (speedup 1.0000x reference)
#include <cuda_runtime.h>
#include <cuda_fp16.h>
#include <math_constants.h>
#include <cstdint>

#define NN    20000
#define KDIM  9480
#define GEDIM 128
#define NCH   297          // ceil(9480/32) k-chunks
#define NMB   313          // m-blocks of 64 rows
#define TOTALU (NMB * NCH) // 92961 chunk-units
#define NCTA  444          // 148 SMs x 3 CTAs -> single wave
#define NPART 3            // max partials per m-block
#define BCHUNKB 8192       // one 128(n)x32(k) half chunk, bytes
// stage: Ahi(4K) Alo(4K) Bhi(8K) Blo(8K) = 24K
#define ST_AHI 0
#define ST_ALO 4096
#define ST_BHI 8192
#define ST_BLO 16384
#define STAGEB 24576
#define GEMM_SMEM (1024 + 2 * STAGEB)

// ---------------- static device scratch (no allocs) ----------------
__device__ float  g_hp[NPART][(size_t)NN * GEDIM];   // partial h per piece-slot
__device__ __half g_Bhi[(size_t)NCH * 4096];          // Wr^T hi, pre-swizzled
__device__ __half g_Blo[(size_t)NCH * 4096];          // Wr^T lo

// ---------------- helpers ----------------
__device__ __forceinline__ uint32_t smem_u32(const void* p) {
    uint32_t a;
    asm("{ .reg .u64 t; cvta.to.shared.u64 t, %1; cvt.u32.u64 %0, t; }"
        : "=r"(a) : "l"(p));
    return a;
}
// swizzle for 64-byte rows: XOR bits[5:4] with bits[8:7]
__device__ __forceinline__ uint32_t swz64(uint32_t b) { return b ^ ((b >> 3) & 0x30); }

__device__ __forceinline__ void ldsm4(uint32_t& r0, uint32_t& r1,
                                      uint32_t& r2, uint32_t& r3, uint32_t a) {
    asm volatile("ldmatrix.sync.aligned.m8n8.x4.shared.b16 {%0,%1,%2,%3}, [%4];"
                 : "=r"(r0), "=r"(r1), "=r"(r2), "=r"(r3) : "r"(a));
}
__device__ __forceinline__ void mma16816(float* c, const uint32_t* a,
                                         const uint32_t* b) {
    asm volatile(
        "mma.sync.aligned.m16n8k16.row.col.f32.f16.f16.f32 "
        "{%0,%1,%2,%3},{%4,%5,%6,%7},{%8,%9},{%0,%1,%2,%3};"
        : "+f"(c[0]), "+f"(c[1]), "+f"(c[2]), "+f"(c[3])
        : "r"(a[0]), "r"(a[1]), "r"(a[2]), "r"(a[3]), "r"(b[0]), "r"(b[1]));
}
#define CP16(dst, src) \
    asm volatile("cp.async.ca.shared.global [%0], [%1], 16;" \
                 :: "r"(dst), "l"(src) : "memory")
#define CP_COMMIT() asm volatile("cp.async.commit_group;" ::: "memory")
#define CP_WAIT1()  asm volatile("cp.async.wait_group 1;" ::: "memory")
#define CP_WAIT0()  asm volatile("cp.async.wait_group 0;" ::: "memory")

union U8h { __half h[8]; uint4 u; };

// largest CTA index p with u_p = floor(p*TOTALU/NCTA) <= U
__device__ __forceinline__ int p_of(int U) {
    return (int)(((long long)U * NCTA + (NCTA - 1)) / TOTALU);
}

// ---------------------------------------------------------------------------
// Prep: g_Bhi/g_Blo = transpose(Wr)*1024, split hi/lo, per-chunk 128(n)x32(k)
// half tiles with 64B-row swizzle. One block per chunk.
// ---------------------------------------------------------------------------
__global__ void __launch_bounds__(256) prep_kernel(const float* __restrict__ Wr)
{
    __shared__ float Ws[32][128];
    const int c = blockIdx.x;
    const int tid = threadIdx.x;

    for (int i = tid; i < 32 * 32; i += 256) {
        const int r = i >> 5;
        const int col = (i & 31) * 4;
        const int gk = c * 32 + r;
        float4 v = make_float4(0.f, 0.f, 0.f, 0.f);
        if (gk < KDIM) v = *reinterpret_cast<const float4*>(Wr + (size_t)gk * GEDIM + col);
        Ws[r][col] = v.x; Ws[r][col + 1] = v.y; Ws[r][col + 2] = v.z; Ws[r][col + 3] = v.w;
    }
    __syncthreads();

    const int n = tid & 127;
    const int sel = tid >> 7;     // 0 -> hi, 1 -> lo
    char* dstBase = reinterpret_cast<char*>(sel ? g_Blo : g_Bhi) + (size_t)c * BCHUNKB;

    for (int grp = 0; grp < 4; grp++) {
        U8h u;
#pragma unroll
        for (int j = 0; j < 8; j++) {
            const float f = Ws[grp * 8 + j][n] * 1024.0f;
            const __half hi = __float2half_rn(f);
            u.h[j] = sel ? __float2half_rn(f - __half2float(hi)) : hi;
        }
        const uint32_t byte = (uint32_t)n * 64 + grp * 16;
        *reinterpret_cast<uint4*>(dstBase + swz64(byte)) = u.u;
    }
}

// ---------------------------------------------------------------------------
// One GEMM piece: rows [m0, m0+64), chunks [c0, c0+nrel), partial -> g_hp[slot].
// Exact R8 inner pipeline: 2-stage, 2-sync, K=32 chunks.
// ---------------------------------------------------------------------------
__device__ __forceinline__ void gemm_piece(const float* __restrict__ x,
                                           char* smem, uint32_t sb,
                                           int m0, int c0, int nrel, int slot)
{
    char* const stg0 = smem + 1024;
    const int tid  = threadIdx.x;
    const int wid  = tid >> 5;
    const int lane = tid & 31;
    const int wm   = wid & 1;
    const int wn   = wid >> 1;

    const int arow = tid >> 2;
    const int aq   = tid & 3;
    const bool rowOk = (m0 + arow) < NN;
    const float* xrow = x + (size_t)(m0 + arow) * KDIM;
    const uint32_t bOff = (uint32_t)tid * 32;

    float acc[2][4][4];
#pragma unroll
    for (int i = 0; i < 2; i++)
#pragma unroll
        for (int j = 0; j < 4; j++)
#pragma unroll
            for (int q = 0; q < 4; q++) acc[i][j][q] = 0.f;

    // ---- prologue: B(c0) cp.async, A(c0) LDG ----
    {
        const char* srcH = reinterpret_cast<const char*>(g_Bhi) + (size_t)c0 * BCHUNKB + bOff;
        const char* srcL = reinterpret_cast<const char*>(g_Blo) + (size_t)c0 * BCHUNKB + bOff;
        CP16(sb + ST_BHI + bOff,      srcH);
        CP16(sb + ST_BHI + bOff + 16, srcH + 16);
        CP16(sb + ST_BLO + bOff,      srcL);
        CP16(sb + ST_BLO + bOff + 16, srcL + 16);
        CP_COMMIT();
    }
    float4 ar[2];
    {
        const int kb = c0 * 32 + aq * 8;
#pragma unroll
        for (int j = 0; j < 2; j++) {
            ar[j] = make_float4(0.f, 0.f, 0.f, 0.f);
            if (rowOk && (kb + j * 4) < KDIM)
                ar[j] = *reinterpret_cast<const float4*>(xrow + kb + j * 4);
        }
    }

    for (int rc = 0; rc < nrel; ++rc) {
        const int s = rc & 1;
        const uint32_t stBase = sb + s * STAGEB;
        char* const stPtr = stg0 + s * STAGEB;
        const bool hasNext = (rc + 1) < nrel;

        float4 arN[2];
        if (hasNext) {
            const int cn = c0 + rc + 1;
            const uint32_t st2 = sb + (s ^ 1) * STAGEB;
            const char* srcH = reinterpret_cast<const char*>(g_Bhi) + (size_t)cn * BCHUNKB + bOff;
            const char* srcL = reinterpret_cast<const char*>(g_Blo) + (size_t)cn * BCHUNKB + bOff;
            CP16(st2 + ST_BHI + bOff,      srcH);
            CP16(st2 + ST_BHI + bOff + 16, srcH + 16);
            CP16(st2 + ST_BLO + bOff,      srcL);
            CP16(st2 + ST_BLO + bOff + 16, srcL + 16);
            CP_COMMIT();
            const int kb = cn * 32 + aq * 8;
#pragma unroll
            for (int j = 0; j < 2; j++) {
                arN[j] = make_float4(0.f, 0.f, 0.f, 0.f);
                if (rowOk && (kb + j * 4) < KDIM)
                    arN[j] = *reinterpret_cast<const float4*>(xrow + kb + j * 4);
            }
        }

        // ---- STS A(rc): split fp32 -> fp16 hi/lo, 64B-row swizzle ----
        {
            const float* vf = reinterpret_cast<const float*>(ar);
            U8h uh, ul;
#pragma unroll
            for (int q = 0; q < 8; q++) {
                const float f = vf[q];
                const __half hi = __float2half_rn(f);
                uh.h[q] = hi;
                ul.h[q] = __float2half_rn(f - __half2float(hi));
            }
            const uint32_t sw = swz64((uint32_t)arow * 64 + aq * 16);
            *reinterpret_cast<uint4*>(stPtr + ST_AHI + sw) = uh.u;
            *reinterpret_cast<uint4*>(stPtr + ST_ALO + sw) = ul.u;
        }

        if (hasNext) { CP_WAIT1(); } else { CP_WAIT0(); }
        __syncthreads();

        // ---- compute chunk (K=32 -> 2 x k16) ----
        {
            const int amrow = wm * 32 + (lane & 15);
            const int akoff = (lane >> 4);
            const int bnrow = wn * 32 + (lane & 7) + ((lane >> 4) & 1) * 8;
            const int bkoff = (lane >> 3) & 1;
#pragma unroll
            for (int k16 = 0; k16 < 2; k16++) {
                uint32_t ah[2][4], al[2][4];
#pragma unroll
                for (int mi = 0; mi < 2; mi++) {
                    const uint32_t byteA =
                        (uint32_t)(amrow + mi * 16) * 64 + (k16 * 2 + akoff) * 16;
                    const uint32_t swA = swz64(byteA);
                    ldsm4(ah[mi][0], ah[mi][1], ah[mi][2], ah[mi][3],
                          stBase + ST_AHI + swA);
                    ldsm4(al[mi][0], al[mi][1], al[mi][2], al[mi][3],
                          stBase + ST_ALO + swA);
                }
#pragma unroll
                for (int np = 0; np < 2; np++) {
                    const uint32_t byteB =
                        (uint32_t)(bnrow + np * 16) * 64 + (k16 * 2 + bkoff) * 16;
                    const uint32_t swB = swz64(byteB);
                    uint32_t bh[4], bl[4];
                    ldsm4(bh[0], bh[1], bh[2], bh[3], stBase + ST_BHI + swB);
                    ldsm4(bl[0], bl[1], bl[2], bl[3], stBase + ST_BLO + swB);
#pragma unroll
                    for (int mi = 0; mi < 2; mi++) {
                        mma16816(acc[mi][np * 2],     ah[mi], bh);
                        mma16816(acc[mi][np * 2],     al[mi], bh);
                        mma16816(acc[mi][np * 2],     ah[mi], bl);
                        mma16816(acc[mi][np * 2 + 1], ah[mi], bh + 2);
                        mma16816(acc[mi][np * 2 + 1], al[mi], bh + 2);
                        mma16816(acc[mi][np * 2 + 1], ah[mi], bl + 2);
                    }
                }
            }
        }
        __syncthreads();
        ar[0] = arN[0]; ar[1] = arN[1];
    }

    // ---- store partial -> g_hp[slot], scale by 1/1024 ----
    {
        const float sc = 1.0f / 1024.0f;
        float* dst = g_hp[slot];
#pragma unroll
        for (int mi = 0; mi < 2; mi++) {
            const int r0 = m0 + wm * 32 + mi * 16 + (lane >> 2);
            const int r1 = r0 + 8;
#pragma unroll
            for (int nf = 0; nf < 4; nf++) {
                const int col = wn * 32 + nf * 8 + 2 * (lane & 3);
                if (r0 < NN) {
                    float2 o = make_float2(acc[mi][nf][0] * sc, acc[mi][nf][1] * sc);
                    *reinterpret_cast<float2*>(&dst[(size_t)r0 * GEDIM + col]) = o;
                }
                if (r1 < NN) {
                    float2 o = make_float2(acc[mi][nf][2] * sc, acc[mi][nf][3] * sc);
                    *reinterpret_cast<float2*>(&dst[(size_t)r1 * GEDIM + col]) = o;
                }
            }
        }
    }
}

// ---------------------------------------------------------------------------
// GEMM: 444 CTAs, single wave; each CTA handles chunk-units
// [u_p, u_{p+1}) of the flattened (m-block, chunk) list; <= 2 pieces.
// ---------------------------------------------------------------------------
__global__ void __launch_bounds__(256, 3) gemm_kernel(const float* __restrict__ x)
{
    extern __shared__ char smem[];
    const uint32_t sb = smem_u32(smem) + 1024;

    const int p  = blockIdx.x;
    const int u0 = (int)(((long long)p * TOTALU) / NCTA);
    const int u1 = (int)(((long long)(p + 1) * TOTALU) / NCTA);

    int u = u0;
#pragma unroll 2
    for (int piece = 0; piece < 2; piece++) {
        if (u >= u1) break;
        const int m      = u / NCH;
        const int cstart = u - m * NCH;
        const int bend   = (m + 1) * NCH;
        const int pend   = (u1 < bend) ? u1 : bend;
        const int nrel   = pend - u;
        const int slot   = p - p_of(m * NCH);
        gemm_piece(x, smem, sb, m * 64, cstart, nrel, slot);
        if (piece == 0 && pend < u1) __syncthreads();
        u = pend;
    }
}

// ---------------------------------------------------------------------------
// Epilogue: 512 threads = 16 samples per block, weights staged in padded smem.
// Number of partial slots per m-block computed from the same schedule formula.
// ---------------------------------------------------------------------------
#define OFF_WE 0
#define OFF_WQ 66048
#define OFF_WK 74752
#define OFF_WV 83456
#define OFF_WO 92160
#define OFF_BE 100864
#define OFF_BQ 101376
#define OFF_BK 101888
#define OFF_BV 102400
#define OFF_BO 102912
#define OFF_BR 103424
#define OFF_H  103936
#define OFF_SC 112128
#define EPI_SMEM 124416

__global__ void __launch_bounds__(512) epilogue_kernel(
    const float* __restrict__ We, const float* __restrict__ be,
    const float* __restrict__ Wq, const float* __restrict__ bq,
    const float* __restrict__ Wk, const float* __restrict__ bk,
    const float* __restrict__ Wv, const float* __restrict__ bv,
    const float* __restrict__ Wo, const float* __restrict__ bo,
    const float* __restrict__ br,
    float* __restrict__ out)
{
    extern __shared__ char sm[];
    float* WE = reinterpret_cast<float*>(sm + OFF_WE);   // [128][129]
    float* WQ = reinterpret_cast<float*>(sm + OFF_WQ);   // [128][17]
    float* WK = reinterpret_cast<float*>(sm + OFF_WK);
    float* WV = reinterpret_cast<float*>(sm + OFF_WV);
    float* WO = reinterpret_cast<float*>(sm + OFF_WO);
    float* BE = reinterpret_cast<float*>(sm + OFF_BE);
    float* BQ = reinterpret_cast<float*>(sm + OFF_BQ);
    float* BK = reinterpret_cast<float*>(sm + OFF_BK);
    float* BV = reinterpret_cast<float*>(sm + OFF_BV);
    float* BO = reinterpret_cast<float*>(sm + OFF_BO);
    float* BR = reinterpret_cast<float*>(sm + OFF_BR);
    float* Hs = reinterpret_cast<float*>(sm + OFF_H);    // [16][128]
    float* SC = reinterpret_cast<float*>(sm + OFF_SC);
    float* eoS = SC;
    float* qS  = SC + 512;
    float* kS  = SC + 1024;
    float* vS  = SC + 1536;
    float* aS  = SC + 2048;
    float* atS = SC + 2560;

    const int tid = threadIdx.x;

    for (int i = tid; i < 128 * 32; i += 512) {
        const int r = i >> 5;
        const int col = (i & 31) * 4;
        float4 w = *reinterpret_cast<const float4*>(We + (size_t)r * 128 + col);
        WE[r * 129 + col] = w.x; WE[r * 129 + col + 1] = w.y;
        WE[r * 129 + col + 2] = w.z; WE[r * 129 + col + 3] = w.w;
    }
    for (int i = tid; i < 2048; i += 512) {
        const int r = i >> 4;
        const int col = i & 15;
        WQ[r * 17 + col] = Wq[i];
        WK[r * 17 + col] = Wk[i];
        WV[r * 17 + col] = Wv[i];
        WO[r * 17 + col] = Wo[i];
    }
    if (tid < 128) {
        BE[tid] = be[tid]; BQ[tid] = bq[tid]; BK[tid] = bk[tid];
        BV[tid] = bv[tid]; BO[tid] = bo[tid]; BR[tid] = br[tid];
    }
    __syncthreads();

    const int warp = tid >> 5;
    const int lane = tid & 31;
    const int n = blockIdx.x * 16 + warp;

    // ---- h = sum of schedule-determined partials + br ----
    float4 hv;
    {
        const int m  = n >> 6;                 // m-block = n / 64
        const int F  = m * NCH;
        const int pf = (int)(((long long)F * NCTA + (NCTA - 1)) / TOTALU);
        const int pl = (int)(((long long)(F + NCH - 1) * NCTA + (NCTA - 1)) / TOTALU);
        const int cnt = pl - pf + 1;           // 2 or 3

        float4 a = reinterpret_cast<const float4*>(&g_hp[0][(size_t)n * GEDIM])[lane];
        float4 b = reinterpret_cast<const float4*>(&g_hp[1][(size_t)n * GEDIM])[lane];
        a.x += b.x; a.y += b.y; a.z += b.z; a.w += b.w;
        if (cnt == 3) {
            float4 c = reinterpret_cast<const float4*>(&g_hp[2][(size_t)n * GEDIM])[lane];
            a.x += c.x; a.y += c.y; a.z += c.z; a.w += c.w;
        }
        hv.x = a.x + BR[lane * 4 + 0];
        hv.y = a.y + BR[lane * 4 + 1];
        hv.z = a.z + BR[lane * 4 + 2];
        hv.w = a.w + BR[lane * 4 + 3];
        *reinterpret_cast<float4*>(&Hs[warp * 128 + lane * 4]) = hv;
    }
    float v[4] = { hv.x, hv.y, hv.z, hv.w };

    // ---- top-1 ----
    float bval = v[0];
    int bidx = lane * 4;
#pragma unroll
    for (int t = 1; t < 4; t++)
        if (v[t] > bval) { bval = v[t]; bidx = lane * 4 + t; }
#pragma unroll
    for (int off = 16; off >= 1; off >>= 1) {
        float ov = __shfl_xor_sync(0xffffffffu, bval, off);
        int   oi = __shfl_xor_sync(0xffffffffu, bidx, off);
        if (ov > bval || (ov == bval && oi < bidx)) { bval = ov; bidx = oi; }
    }
    const float m1 = bval;
    const int   i1 = bidx;

    // ---- top-2 ----
    bval = -CUDART_INF_F;
    bidx = 1 << 30;
#pragma unroll
    for (int t = 0; t < 4; t++) {
        const int idx = lane * 4 + t;
        if (idx != i1 && v[t] > bval) { bval = v[t]; bidx = idx; }
    }
#pragma unroll
    for (int off = 16; off >= 1; off >>= 1) {
        float ov = __shfl_xor_sync(0xffffffffu, bval, off);
        int   oi = __shfl_xor_sync(0xffffffffu, bidx, off);
        if (ov > bval || (ov == bval && oi < bidx)) { bval = ov; bidx = oi; }
    }
    const float m2 = bval;
    const int   i2 = bidx;

    const float e2v = __expf(m2 - m1);
    const float inv = 1.0f / (1.0f + e2v);
    const float w1 = inv, w2 = e2v * inv;

    const int side   = lane >> 4;
    const int l      = lane & 15;
    const int target = side ? i2 : i1;
    const float wsel = side ? w2 : w1;
    const int g = target >> 4;
    const int f = target & 15;

    __syncwarp();

    // ---- eo for all 16 experts of selected group ----
    {
        const float* hrow = &Hs[warp * 128];
        const float* wrow = &WE[(g * 16 + l) * 129];
        float acc = BE[g * 16 + l];
#pragma unroll 8
        for (int k = 0; k < 128; k++) acc += hrow[k] * wrow[k];
        eoS[warp * 32 + lane] = acc;
    }
    __syncwarp();

    // ---- Q/K/V projections ----
    {
        const float* wqr = &WQ[(g * 16 + l) * 17];
        const float* wkr = &WK[(g * 16 + l) * 17];
        const float* wvr = &WV[(g * 16 + l) * 17];
        float q  = BQ[g * 16 + l];
        float kk = BK[g * 16 + l];
        float vv = BV[g * 16 + l];
#pragma unroll
        for (int e = 0; e < 16; e++) {
            const float eo = eoS[warp * 32 + side * 16 + e];
            q  += eo * wqr[e];
            kk += eo * wkr[e];
            vv += eo * wvr[e];
        }
        qS[warp * 32 + lane] = q;
        kS[warp * 32 + lane] = kk;
        vS[warp * 32 + lane] = vv;
    }
    __syncwarp();

    // ---- scores + softmax ----
    {
        const int d = l >> 2, e = l & 3;
        float s = 0.f;
#pragma unroll
        for (int h = 0; h < 4; h++)
            s += qS[warp * 32 + side * 16 + h * 4 + d] *
                 kS[warp * 32 + side * 16 + h * 4 + e];
        s *= 0.5f;
        float mx = s;
        mx = fmaxf(mx, __shfl_xor_sync(0xffffffffu, mx, 1));
        mx = fmaxf(mx, __shfl_xor_sync(0xffffffffu, mx, 2));
        float p = __expf(s - mx);
        float smv = p;
        smv += __shfl_xor_sync(0xffffffffu, smv, 1);
        smv += __shfl_xor_sync(0xffffffffu, smv, 2);
        p /= smv;
        aS[warp * 32 + lane] = p;
    }
    __syncwarp();

    // ---- att ----
    {
        const int h_ = l >> 2, dd = l & 3;
        float att = 0.f;
#pragma unroll
        for (int e = 0; e < 4; e++)
            att += aS[warp * 32 + side * 16 + dd * 4 + e] *
                   vS[warp * 32 + side * 16 + h_ * 4 + e];
        atS[warp * 32 + lane] = att;
    }
    __syncwarp();

    // ---- out + gate ----
    {
        const float* wor = &WO[(g * 16 + f) * 17];
        float t = atS[warp * 32 + side * 16 + l] * wor[l];
#pragma unroll
        for (int off = 8; off >= 1; off >>= 1)
            t += __shfl_xor_sync(0xffffffffu, t, off);
        t += BO[g * 16 + f];
        const float res = wsel * t;
        const float tot = res + __shfl_xor_sync(0xffffffffu, res, 16);
        if (lane == 0) out[n] = tot;
    }
}

// ---------------------------------------------------------------------------
extern "C" void kernel_launch(void* const* d_in, const int* in_sizes, int n_in,
                              void* d_out, int out_size)
{
    const float* x  = (const float*)d_in[0];
    const float* Wr = (const float*)d_in[1];
    const float* br = (const float*)d_in[2];
    const float* We = (const float*)d_in[3];
    const float* be = (const float*)d_in[4];
    const float* Wq = (const float*)d_in[5];
    const float* bq = (const float*)d_in[6];
    const float* Wk = (const float*)d_in[7];
    const float* bk = (const float*)d_in[8];
    const float* Wv = (const float*)d_in[9];
    const float* bv = (const float*)d_in[10];
    const float* Wo = (const float*)d_in[11];
    const float* bo = (const float*)d_in[12];
    float* out = (float*)d_out;

    static bool attr_done = false;
    if (!attr_done) {
        cudaFuncSetAttribute(gemm_kernel,
            cudaFuncAttributeMaxDynamicSharedMemorySize, GEMM_SMEM);
        cudaFuncSetAttribute(epilogue_kernel,
            cudaFuncAttributeMaxDynamicSharedMemorySize, EPI_SMEM);
        attr_done = true;
    }

    prep_kernel<<<NCH, 256>>>(Wr);
    gemm_kernel<<<NCTA, 256, GEMM_SMEM>>>(x);
    epilogue_kernel<<<1250, 512, EPI_SMEM>>>(We, be, Wq, bq, Wk, bk,
                                             Wv, bv, Wo, bo, br, out);
}

// round 15
// speedup vs baseline: 1.1815x; 1.1815x over previous
#include <cuda_runtime.h>
#include <cuda_fp16.h>
#include <math_constants.h>
#include <cstdint>

#define NN    20000
#define KDIM  9480
#define GEDIM 128
#define NCH   297          // ceil(9480/32)
#define NSPLIT 4
#define CPS   75           // chunks per split (last split: 72)
#define BCHUNKB 8192       // one 128(n)x32(k) half chunk, bytes
// stage: Ahi(4K) Alo(4K) Bhi(8K) Blo(8K) = 24K
#define ST_AHI 0
#define ST_ALO 4096
#define ST_BHI 8192
#define ST_BLO 16384
#define STAGEB 24576
#define GEMM_SMEM (1024 + 2 * STAGEB)

// ---------------- static device scratch (no allocs) ----------------
__device__ float  g_hp[NSPLIT][(size_t)NN * GEDIM];   // partial h per K-split
__device__ __half g_Bhi[(size_t)NCH * 4096];          // Wr^T hi, pre-swizzled
__device__ __half g_Blo[(size_t)NCH * 4096];          // Wr^T lo

// ---------------- helpers ----------------
__device__ __forceinline__ uint32_t smem_u32(const void* p) {
    uint32_t a;
    asm("{ .reg .u64 t; cvta.to.shared.u64 t, %1; cvt.u32.u64 %0, t; }"
        : "=r"(a) : "l"(p));
    return a;
}
// swizzle for 64-byte rows: XOR bits[5:4] with bits[8:7]
__device__ __forceinline__ uint32_t swz64(uint32_t b) { return b ^ ((b >> 3) & 0x30); }

__device__ __forceinline__ void ldsm4(uint32_t& r0, uint32_t& r1,
                                      uint32_t& r2, uint32_t& r3, uint32_t a) {
    asm volatile("ldmatrix.sync.aligned.m8n8.x4.shared.b16 {%0,%1,%2,%3}, [%4];"
                 : "=r"(r0), "=r"(r1), "=r"(r2), "=r"(r3) : "r"(a));
}
__device__ __forceinline__ void mma16816(float* c, const uint32_t* a,
                                         const uint32_t* b) {
    asm volatile(
        "mma.sync.aligned.m16n8k16.row.col.f32.f16.f16.f32 "
        "{%0,%1,%2,%3},{%4,%5,%6,%7},{%8,%9},{%0,%1,%2,%3};"
        : "+f"(c[0]), "+f"(c[1]), "+f"(c[2]), "+f"(c[3])
        : "r"(a[0]), "r"(a[1]), "r"(a[2]), "r"(a[3]), "r"(b[0]), "r"(b[1]));
}
// .cg: L2-only fill — B chunks are shared across CTAs and L2-resident;
// skipping the L1 fill leaves L1 for x LDGs and the LDSM-heavy compute phase.
#define CP16(dst, src) \
    asm volatile("cp.async.cg.shared.global [%0], [%1], 16;" \
                 :: "r"(dst), "l"(src) : "memory")
#define CP_COMMIT() asm volatile("cp.async.commit_group;" ::: "memory")
#define CP_WAIT1()  asm volatile("cp.async.wait_group 1;" ::: "memory")
#define CP_WAIT0()  asm volatile("cp.async.wait_group 0;" ::: "memory")

union U8h { __half h[8]; uint4 u; };

// ---------------------------------------------------------------------------
// Prep: g_Bhi/g_Blo = transpose(Wr)*1024, split hi/lo, per-chunk 128(n)x32(k)
// half tiles with 64B-row swizzle. One block per chunk.
// ---------------------------------------------------------------------------
__global__ void __launch_bounds__(256) prep_kernel(const float* __restrict__ Wr)
{
    __shared__ float Ws[32][128];
    const int c = blockIdx.x;
    const int tid = threadIdx.x;

    for (int i = tid; i < 32 * 32; i += 256) {
        const int r = i >> 5;
        const int col = (i & 31) * 4;
        const int gk = c * 32 + r;
        float4 v = make_float4(0.f, 0.f, 0.f, 0.f);
        if (gk < KDIM) v = *reinterpret_cast<const float4*>(Wr + (size_t)gk * GEDIM + col);
        Ws[r][col] = v.x; Ws[r][col + 1] = v.y; Ws[r][col + 2] = v.z; Ws[r][col + 3] = v.w;
    }
    __syncthreads();

    const int n = tid & 127;
    const int sel = tid >> 7;     // 0 -> hi, 1 -> lo
    char* dstBase = reinterpret_cast<char*>(sel ? g_Blo : g_Bhi) + (size_t)c * BCHUNKB;

    for (int grp = 0; grp < 4; grp++) {
        U8h u;
#pragma unroll
        for (int j = 0; j < 8; j++) {
            const float f = Ws[grp * 8 + j][n] * 1024.0f;
            const __half hi = __float2half_rn(f);
            u.h[j] = sel ? __float2half_rn(f - __half2float(hi)) : hi;
        }
        const uint32_t byte = (uint32_t)n * 64 + grp * 16;
        *reinterpret_cast<uint4*>(dstBase + swz64(byte)) = u.u;
    }
}

// ---------------------------------------------------------------------------
// GEMM via mma.sync m16n8k16, fp16 3-product split, fp32 accum.
// grid (313, NSPLIT); 256 threads; 64x128 tile; K chunks of 32;
// 2-stage pipeline; 3 CTAs/SM (6 warps/SMSP).
// ---------------------------------------------------------------------------
__global__ void __launch_bounds__(256, 3) gemm_kernel(const float* __restrict__ x)
{
    extern __shared__ char smem[];
    const uint32_t sb = smem_u32(smem) + 1024;
    char* const stg0 = smem + 1024;

    const int tid  = threadIdx.x;
    const int wid  = tid >> 5;
    const int lane = tid & 31;
    const int wm   = wid & 1;         // M half (32 rows)
    const int wn   = wid >> 1;        // N quadrant (32 cols)
    const int m0   = blockIdx.x * 64;
    const int split = blockIdx.y;
    const int c0 = split * CPS;
    const int c1 = (c0 + CPS < NCH) ? c0 + CPS : NCH;
    const int nrel = c1 - c0;

    // A producer: 256 threads -> 64 rows x 4 k-eighths (8 floats each)
    const int arow = tid >> 2;
    const int aq   = tid & 3;
    const bool rowOk = (m0 + arow) < NN;
    const float* xrow = x + (size_t)(m0 + arow) * KDIM;

    // B producer: 32B of hi + 32B of lo per thread
    const uint32_t bOff = (uint32_t)tid * 32;

    float acc[2][4][4];
#pragma unroll
    for (int i = 0; i < 2; i++)
#pragma unroll
        for (int j = 0; j < 4; j++)
#pragma unroll
            for (int q = 0; q < 4; q++) acc[i][j][q] = 0.f;

    // ---- prologue: B(c0) cp.async, A(c0) LDG ----
    {
        const char* srcH = reinterpret_cast<const char*>(g_Bhi) + (size_t)c0 * BCHUNKB + bOff;
        const char* srcL = reinterpret_cast<const char*>(g_Blo) + (size_t)c0 * BCHUNKB + bOff;
        CP16(sb + ST_BHI + bOff,      srcH);
        CP16(sb + ST_BHI + bOff + 16, srcH + 16);
        CP16(sb + ST_BLO + bOff,      srcL);
        CP16(sb + ST_BLO + bOff + 16, srcL + 16);
        CP_COMMIT();
    }
    float4 ar[2];
    {
        const int kb = c0 * 32 + aq * 8;
#pragma unroll
        for (int j = 0; j < 2; j++) {
            ar[j] = make_float4(0.f, 0.f, 0.f, 0.f);
            if (rowOk && (kb + j * 4) < KDIM)
                ar[j] = *reinterpret_cast<const float4*>(xrow + kb + j * 4);
        }
    }

    for (int rc = 0; rc < nrel; ++rc) {
        const int s = rc & 1;
        const uint32_t stBase = sb + s * STAGEB;
        char* const stPtr = stg0 + s * STAGEB;
        const bool hasNext = (rc + 1) < nrel;

        float4 arN[2];
        if (hasNext) {
            const int cn = c0 + rc + 1;
            const uint32_t st2 = sb + (s ^ 1) * STAGEB;
            const char* srcH = reinterpret_cast<const char*>(g_Bhi) + (size_t)cn * BCHUNKB + bOff;
            const char* srcL = reinterpret_cast<const char*>(g_Blo) + (size_t)cn * BCHUNKB + bOff;
            CP16(st2 + ST_BHI + bOff,      srcH);
            CP16(st2 + ST_BHI + bOff + 16, srcH + 16);
            CP16(st2 + ST_BLO + bOff,      srcL);
            CP16(st2 + ST_BLO + bOff + 16, srcL + 16);
            CP_COMMIT();
            const int kb = cn * 32 + aq * 8;
#pragma unroll
            for (int j = 0; j < 2; j++) {
                arN[j] = make_float4(0.f, 0.f, 0.f, 0.f);
                if (rowOk && (kb + j * 4) < KDIM)
                    arN[j] = *reinterpret_cast<const float4*>(xrow + kb + j * 4);
            }
        }

        // ---- STS A(rc): split fp32 -> fp16 hi/lo, 64B-row swizzle ----
        {
            const float* vf = reinterpret_cast<const float*>(ar);
            U8h uh, ul;
#pragma unroll
            for (int q = 0; q < 8; q++) {
                const float f = vf[q];
                const __half hi = __float2half_rn(f);
                uh.h[q] = hi;
                ul.h[q] = __float2half_rn(f - __half2float(hi));
            }
            const uint32_t sw = swz64((uint32_t)arow * 64 + aq * 16);
            *reinterpret_cast<uint4*>(stPtr + ST_AHI + sw) = uh.u;
            *reinterpret_cast<uint4*>(stPtr + ST_ALO + sw) = ul.u;
        }

        if (hasNext) { CP_WAIT1(); } else { CP_WAIT0(); }
        __syncthreads();

        // ---- compute chunk (K=32 -> 2 x k16) ----
        {
            const int amrow = wm * 32 + (lane & 15);
            const int akoff = (lane >> 4);               // 0/1 (16B chunk)
            const int bnrow = wn * 32 + (lane & 7) + ((lane >> 4) & 1) * 8;
            const int bkoff = (lane >> 3) & 1;
#pragma unroll
            for (int k16 = 0; k16 < 2; k16++) {
                uint32_t ah[2][4], al[2][4];
#pragma unroll
                for (int mi = 0; mi < 2; mi++) {
                    const uint32_t byteA =
                        (uint32_t)(amrow + mi * 16) * 64 + (k16 * 2 + akoff) * 16;
                    const uint32_t swA = swz64(byteA);
                    ldsm4(ah[mi][0], ah[mi][1], ah[mi][2], ah[mi][3],
                          stBase + ST_AHI + swA);
                    ldsm4(al[mi][0], al[mi][1], al[mi][2], al[mi][3],
                          stBase + ST_ALO + swA);
                }
#pragma unroll
                for (int np = 0; np < 2; np++) {
                    const uint32_t byteB =
                        (uint32_t)(bnrow + np * 16) * 64 + (k16 * 2 + bkoff) * 16;
                    const uint32_t swB = swz64(byteB);
                    uint32_t bh[4], bl[4];
                    ldsm4(bh[0], bh[1], bh[2], bh[3], stBase + ST_BHI + swB);
                    ldsm4(bl[0], bl[1], bl[2], bl[3], stBase + ST_BLO + swB);
#pragma unroll
                    for (int mi = 0; mi < 2; mi++) {
                        mma16816(acc[mi][np * 2],     ah[mi], bh);
                        mma16816(acc[mi][np * 2],     al[mi], bh);
                        mma16816(acc[mi][np * 2],     ah[mi], bl);
                        mma16816(acc[mi][np * 2 + 1], ah[mi], bh + 2);
                        mma16816(acc[mi][np * 2 + 1], al[mi], bh + 2);
                        mma16816(acc[mi][np * 2 + 1], ah[mi], bl + 2);
                    }
                }
            }
        }
        __syncthreads();
        ar[0] = arN[0]; ar[1] = arN[1];
    }

    // ---- store C -> g_hp[split], scale by 1/1024 ----
    {
        const float sc = 1.0f / 1024.0f;
        float* dst = g_hp[split];
#pragma unroll
        for (int mi = 0; mi < 2; mi++) {
            const int r0 = m0 + wm * 32 + mi * 16 + (lane >> 2);
            const int r1 = r0 + 8;
#pragma unroll
            for (int nf = 0; nf < 4; nf++) {
                const int col = wn * 32 + nf * 8 + 2 * (lane & 3);
                if (r0 < NN) {
                    float2 o = make_float2(acc[mi][nf][0] * sc, acc[mi][nf][1] * sc);
                    *reinterpret_cast<float2*>(&dst[(size_t)r0 * GEDIM + col]) = o;
                }
                if (r1 < NN) {
                    float2 o = make_float2(acc[mi][nf][2] * sc, acc[mi][nf][3] * sc);
                    *reinterpret_cast<float2*>(&dst[(size_t)r1 * GEDIM + col]) = o;
                }
            }
        }
    }
}

// ---------------------------------------------------------------------------
// Epilogue: 512 threads = 16 samples per block, weights staged in padded smem.
// ---------------------------------------------------------------------------
#define OFF_WE 0
#define OFF_WQ 66048
#define OFF_WK 74752
#define OFF_WV 83456
#define OFF_WO 92160
#define OFF_BE 100864
#define OFF_BQ 101376
#define OFF_BK 101888
#define OFF_BV 102400
#define OFF_BO 102912
#define OFF_BR 103424
#define OFF_H  103936
#define OFF_SC 112128
#define EPI_SMEM 124416

__global__ void __launch_bounds__(512) epilogue_kernel(
    const float* __restrict__ We, const float* __restrict__ be,
    const float* __restrict__ Wq, const float* __restrict__ bq,
    const float* __restrict__ Wk, const float* __restrict__ bk,
    const float* __restrict__ Wv, const float* __restrict__ bv,
    const float* __restrict__ Wo, const float* __restrict__ bo,
    const float* __restrict__ br,
    float* __restrict__ out)
{
    extern __shared__ char sm[];
    float* WE = reinterpret_cast<float*>(sm + OFF_WE);   // [128][129]
    float* WQ = reinterpret_cast<float*>(sm + OFF_WQ);   // [128][17]
    float* WK = reinterpret_cast<float*>(sm + OFF_WK);
    float* WV = reinterpret_cast<float*>(sm + OFF_WV);
    float* WO = reinterpret_cast<float*>(sm + OFF_WO);
    float* BE = reinterpret_cast<float*>(sm + OFF_BE);
    float* BQ = reinterpret_cast<float*>(sm + OFF_BQ);
    float* BK = reinterpret_cast<float*>(sm + OFF_BK);
    float* BV = reinterpret_cast<float*>(sm + OFF_BV);
    float* BO = reinterpret_cast<float*>(sm + OFF_BO);
    float* BR = reinterpret_cast<float*>(sm + OFF_BR);
    float* Hs = reinterpret_cast<float*>(sm + OFF_H);    // [16][128]
    float* SC = reinterpret_cast<float*>(sm + OFF_SC);
    float* eoS = SC;
    float* qS  = SC + 512;
    float* kS  = SC + 1024;
    float* vS  = SC + 1536;
    float* aS  = SC + 2048;
    float* atS = SC + 2560;

    const int tid = threadIdx.x;

    for (int i = tid; i < 128 * 32; i += 512) {
        const int r = i >> 5;
        const int col = (i & 31) * 4;
        float4 w = *reinterpret_cast<const float4*>(We + (size_t)r * 128 + col);
        WE[r * 129 + col] = w.x; WE[r * 129 + col + 1] = w.y;
        WE[r * 129 + col + 2] = w.z; WE[r * 129 + col + 3] = w.w;
    }
    for (int i = tid; i < 2048; i += 512) {
        const int r = i >> 4;
        const int col = i & 15;
        WQ[r * 17 + col] = Wq[i];
        WK[r * 17 + col] = Wk[i];
        WV[r * 17 + col] = Wv[i];
        WO[r * 17 + col] = Wo[i];
    }
    if (tid < 128) {
        BE[tid] = be[tid]; BQ[tid] = bq[tid]; BK[tid] = bk[tid];
        BV[tid] = bv[tid]; BO[tid] = bo[tid]; BR[tid] = br[tid];
    }
    __syncthreads();

    const int warp = tid >> 5;
    const int lane = tid & 31;
    const int n = blockIdx.x * 16 + warp;

    // ---- h = sum of NSPLIT partials + br ----
    float4 hv;
    {
        float4 a = reinterpret_cast<const float4*>(&g_hp[0][(size_t)n * GEDIM])[lane];
#pragma unroll
        for (int s = 1; s < NSPLIT; s++) {
            float4 b = reinterpret_cast<const float4*>(&g_hp[s][(size_t)n * GEDIM])[lane];
            a.x += b.x; a.y += b.y; a.z += b.z; a.w += b.w;
        }
        hv.x = a.x + BR[lane * 4 + 0];
        hv.y = a.y + BR[lane * 4 + 1];
        hv.z = a.z + BR[lane * 4 + 2];
        hv.w = a.w + BR[lane * 4 + 3];
        *reinterpret_cast<float4*>(&Hs[warp * 128 + lane * 4]) = hv;
    }
    float v[4] = { hv.x, hv.y, hv.z, hv.w };

    // ---- top-1 ----
    float bval = v[0];
    int bidx = lane * 4;
#pragma unroll
    for (int t = 1; t < 4; t++)
        if (v[t] > bval) { bval = v[t]; bidx = lane * 4 + t; }
#pragma unroll
    for (int off = 16; off >= 1; off >>= 1) {
        float ov = __shfl_xor_sync(0xffffffffu, bval, off);
        int   oi = __shfl_xor_sync(0xffffffffu, bidx, off);
        if (ov > bval || (ov == bval && oi < bidx)) { bval = ov; bidx = oi; }
    }
    const float m1 = bval;
    const int   i1 = bidx;

    // ---- top-2 ----
    bval = -CUDART_INF_F;
    bidx = 1 << 30;
#pragma unroll
    for (int t = 0; t < 4; t++) {
        const int idx = lane * 4 + t;
        if (idx != i1 && v[t] > bval) { bval = v[t]; bidx = idx; }
    }
#pragma unroll
    for (int off = 16; off >= 1; off >>= 1) {
        float ov = __shfl_xor_sync(0xffffffffu, bval, off);
        int   oi = __shfl_xor_sync(0xffffffffu, bidx, off);
        if (ov > bval || (ov == bval && oi < bidx)) { bval = ov; bidx = oi; }
    }
    const float m2 = bval;
    const int   i2 = bidx;

    const float e2v = __expf(m2 - m1);
    const float inv = 1.0f / (1.0f + e2v);
    const float w1 = inv, w2 = e2v * inv;

    const int side   = lane >> 4;
    const int l      = lane & 15;
    const int target = side ? i2 : i1;
    const float wsel = side ? w2 : w1;
    const int g = target >> 4;
    const int f = target & 15;

    __syncwarp();

    // ---- eo for all 16 experts of selected group ----
    {
        const float* hrow = &Hs[warp * 128];
        const float* wrow = &WE[(g * 16 + l) * 129];
        float acc = BE[g * 16 + l];
#pragma unroll 8
        for (int k = 0; k < 128; k++) acc += hrow[k] * wrow[k];
        eoS[warp * 32 + lane] = acc;
    }
    __syncwarp();

    // ---- Q/K/V projections ----
    {
        const float* wqr = &WQ[(g * 16 + l) * 17];
        const float* wkr = &WK[(g * 16 + l) * 17];
        const float* wvr = &WV[(g * 16 + l) * 17];
        float q  = BQ[g * 16 + l];
        float kk = BK[g * 16 + l];
        float vv = BV[g * 16 + l];
#pragma unroll
        for (int e = 0; e < 16; e++) {
            const float eo = eoS[warp * 32 + side * 16 + e];
            q  += eo * wqr[e];
            kk += eo * wkr[e];
            vv += eo * wvr[e];
        }
        qS[warp * 32 + lane] = q;
        kS[warp * 32 + lane] = kk;
        vS[warp * 32 + lane] = vv;
    }
    __syncwarp();

    // ---- scores + softmax ----
    {
        const int d = l >> 2, e = l & 3;
        float s = 0.f;
#pragma unroll
        for (int h = 0; h < 4; h++)
            s += qS[warp * 32 + side * 16 + h * 4 + d] *
                 kS[warp * 32 + side * 16 + h * 4 + e];
        s *= 0.5f;
        float mx = s;
        mx = fmaxf(mx, __shfl_xor_sync(0xffffffffu, mx, 1));
        mx = fmaxf(mx, __shfl_xor_sync(0xffffffffu, mx, 2));
        float p = __expf(s - mx);
        float smv = p;
        smv += __shfl_xor_sync(0xffffffffu, smv, 1);
        smv += __shfl_xor_sync(0xffffffffu, smv, 2);
        p /= smv;
        aS[warp * 32 + lane] = p;
    }
    __syncwarp();

    // ---- att ----
    {
        const int h_ = l >> 2, dd = l & 3;
        float att = 0.f;
#pragma unroll
        for (int e = 0; e < 4; e++)
            att += aS[warp * 32 + side * 16 + dd * 4 + e] *
                   vS[warp * 32 + side * 16 + h_ * 4 + e];
        atS[warp * 32 + lane] = att;
    }
    __syncwarp();

    // ---- out + gate ----
    {
        const float* wor = &WO[(g * 16 + f) * 17];
        float t = atS[warp * 32 + side * 16 + l] * wor[l];
#pragma unroll
        for (int off = 8; off >= 1; off >>= 1)
            t += __shfl_xor_sync(0xffffffffu, t, off);
        t += BO[g * 16 + f];
        const float res = wsel * t;
        const float tot = res + __shfl_xor_sync(0xffffffffu, res, 16);
        if (lane == 0) out[n] = tot;
    }
}

// ---------------------------------------------------------------------------
extern "C" void kernel_launch(void* const* d_in, const int* in_sizes, int n_in,
                              void* d_out, int out_size)
{
    const float* x  = (const float*)d_in[0];
    const float* Wr = (const float*)d_in[1];
    const float* br = (const float*)d_in[2];
    const float* We = (const float*)d_in[3];
    const float* be = (const float*)d_in[4];
    const float* Wq = (const float*)d_in[5];
    const float* bq = (const float*)d_in[6];
    const float* Wk = (const float*)d_in[7];
    const float* bk = (const float*)d_in[8];
    const float* Wv = (const float*)d_in[9];
    const float* bv = (const float*)d_in[10];
    const float* Wo = (const float*)d_in[11];
    const float* bo = (const float*)d_in[12];
    float* out = (float*)d_out;

    static bool attr_done = false;
    if (!attr_done) {
        cudaFuncSetAttribute(gemm_kernel,
            cudaFuncAttributeMaxDynamicSharedMemorySize, GEMM_SMEM);
        cudaFuncSetAttribute(epilogue_kernel,
            cudaFuncAttributeMaxDynamicSharedMemorySize, EPI_SMEM);
        attr_done = true;
    }

    prep_kernel<<<NCH, 256>>>(Wr);
    gemm_kernel<<<dim3(313, NSPLIT), 256, GEMM_SMEM>>>(x);
    epilogue_kernel<<<1250, 512, EPI_SMEM>>>(We, be, Wq, bq, Wk, bk,
                                             Wv, bv, Wo, bo, br, out);
}